// round 11
// baseline (speedup 1.0000x reference)
#include <cuda_runtime.h>
#include <cstdint>

// Shapes (fixed by this problem instance)
#define BNTOT 828      // B*N
#define LDIM 96
#define SDIM 96
#define HDIM 8
#define EDIM 64
#define DDIM 64

#define TL   32        // l-rows per CTA (3 tiles per bn)
#define ECH  8         // e per chunk (8 chunks per s-pass), phase 1
#define VCHS 12        // s per V chunk (8 chunks), phase 3

// smem strides (floats); conflicts checked per-instruction
#define QST2 12        // Q [h][l][e'] rows of 8e + 4 pad  (stride/4 = 3, odd)
#define KST2 12        // K [h][s][e'] same
#define VST  68        // V [h][s][d]  rows of 64d + 4 pad
#define SP   98        // P [h][l][s]  rows of 96s + 2 pad (even -> 8B-aligned ss-pairs)

// smem float offsets
#define QBSZ   (HDIM*TL*QST2)        // 3072
#define K_OFF  (2*QBSZ)              // 6144
#define KBSZ   (HDIM*SDIM*KST2)      // 9216
#define P_OFF  (K_OFF + 2*KBSZ)      // 24576
#define P_SZ   (HDIM*TL*SP)          // 25088
#define GB_OFF (P_OFF + P_SZ)        // 49664
#define SMEM_FLOATS (GB_OFF + 16)    // 49680
#define SMEM_BYTES  (SMEM_FLOATS*4)  // 198720 B
#define VBSZ   (HDIM*VCHS*VST)       // 6528 (x2 buffers alias Q/K region: 13056 < 24576)

#define SCORES_ELEMS ((size_t)BNTOT * HDIM * LDIM * SDIM)

typedef unsigned long long ull;

__device__ __forceinline__ ull pack2(float x) {
    ull r;
    asm("mov.b64 %0, {%1, %1};" : "=l"(r) : "f"(x));
    return r;
}
__device__ __forceinline__ void fma2(ull &d, ull a, ull b) {
    asm("fma.rn.f32x2 %0, %1, %2, %0;" : "+l"(d) : "l"(a), "l"(b));
}
__device__ __forceinline__ float2 unpack2(ull a) {
    float2 f;
    asm("mov.b64 {%0, %1}, %2;" : "=f"(f.x), "=f"(f.y) : "l"(a));
    return f;
}
__device__ __forceinline__ void cp16(uint32_t dst, const float* src) {
    asm volatile("cp.async.ca.shared.global [%0], [%1], 16;" :: "r"(dst), "l"(src));
}
__device__ __forceinline__ void cp_commit() {
    asm volatile("cp.async.commit_group;" ::: "memory");
}
template <int N> __device__ __forceinline__ void cp_wait() {
    asm volatile("cp.async.wait_group %0;" :: "n"(N) : "memory");
}

__global__ __launch_bounds__(1024, 1)
void stadd_kernel(const float* __restrict__ qg,
                  const float* __restrict__ kg,
                  const float* __restrict__ vg,
                  const float* __restrict__ maskg,
                  const float* __restrict__ asg,
                  const float* __restrict__ gammag,
                  const float* __restrict__ betag,
                  float* __restrict__ scores_out,
                  float* __restrict__ vout)
{
    extern __shared__ float sm[];
    const uint32_t smb = (uint32_t)__cvta_generic_to_shared(sm);
    const int bn   = blockIdx.x / 3;
    const int lt   = blockIdx.x % 3;
    const int l0   = lt * TL;
    const int tid  = threadIdx.x;
    const int warp = tid >> 5;
    const int lane = tid & 31;
    const int h1   = warp >> 2;   // head (4 warps per head)
    const int hq   = warp & 3;    // s-quarter-of-48 (ph1) / d-quarter (ph3)
    const int lq   = lane >> 2;   // 0..7 -> l = lq + 8i (interleaved, conflict-free)
    const int sq   = lane & 3;    // 0..3 -> 3 s (ph1) / 4 d (ph3)

    if (tid < HDIM) { sm[GB_OFF + tid] = gammag[tid]; sm[GB_OFF + 8 + tid] = betag[tid]; }

    // ---- staging: natural e-minor layout via contiguous 16B cp.async (no transpose)
    auto stageQK = [&](int ec, int b) {
        // K chunk: 8h*96s*2 float4 = 1536
        {
            const int fidx = tid;                 // r=0
            const int hh = fidx / 192;
            const int rem = fidx - hh * 192;
            const int s = rem >> 1, f4 = rem & 1;
            cp16(smb + (uint32_t)(K_OFF + b * KBSZ + (hh * SDIM + s) * KST2 + f4 * 4) * 4u,
                 kg + (((size_t)bn * SDIM + s) * HDIM + hh) * EDIM + ec * ECH + f4 * 4);
        }
        if (tid < 512) {                          // r=1
            const int fidx = tid + 1024;
            const int hh = fidx / 192;
            const int rem = fidx - hh * 192;
            const int s = rem >> 1, f4 = rem & 1;
            cp16(smb + (uint32_t)(K_OFF + b * KBSZ + (hh * SDIM + s) * KST2 + f4 * 4) * 4u,
                 kg + (((size_t)bn * SDIM + s) * HDIM + hh) * EDIM + ec * ECH + f4 * 4);
        }
        // Q chunk: 8h*32l*2 float4 = 512
        if (tid < 512) {
            const int hh = tid / 64;
            const int rem = tid - hh * 64;
            const int l = rem >> 1, f4 = rem & 1;
            cp16(smb + (uint32_t)(b * QBSZ + (hh * TL + l) * QST2 + f4 * 4) * 4u,
                 qg + (((size_t)bn * LDIM + l0 + l) * HDIM + hh) * EDIM + ec * ECH + f4 * 4);
        }
        cp_commit();
    };

    // ================= Phase 1: P = Q.K  (dot form, two s-passes of 48)
    // lane tile: 4l (l = lq+8i) x 3s (s = sp*48 + hq*12 + sq*3 + j)
    ull acc[4][3];
    #pragma unroll
    for (int i = 0; i < 4; i++)
        #pragma unroll
        for (int j = 0; j < 3; j++) acc[i][j] = 0ull;

    stageQK(0, 0);
    const float* qb0 = sm + (h1 * TL + lq) * QST2;
    const float* kb0 = sm + K_OFF + h1 * (SDIM * KST2);

    #pragma unroll 1
    for (int r = 0; r < 16; r++) {
        const int sp  = r >> 3;
        const int ec  = r & 7;
        const int buf = r & 1;

        cp_wait<0>();
        __syncthreads();
        if (r < 15) stageQK((ec + 1) & 7, buf ^ 1);   // writes buf^1: last read 2 rounds ago

        const float* q = qb0 + buf * QBSZ;
        const float* k = kb0 + buf * KBSZ + (sp * 48 + hq * 12 + sq * 3) * KST2;

        #pragma unroll
        for (int e4 = 0; e4 < 2; e4++) {
            const ulonglong2 k0 = *reinterpret_cast<const ulonglong2*>(k + 0 * KST2 + e4 * 4);
            const ulonglong2 k1 = *reinterpret_cast<const ulonglong2*>(k + 1 * KST2 + e4 * 4);
            const ulonglong2 k2 = *reinterpret_cast<const ulonglong2*>(k + 2 * KST2 + e4 * 4);
            #pragma unroll
            for (int i = 0; i < 4; i++) {
                const ulonglong2 qv = *reinterpret_cast<const ulonglong2*>(q + i * 8 * QST2 + e4 * 4);
                fma2(acc[i][0], qv.x, k0.x); fma2(acc[i][0], qv.y, k0.y);
                fma2(acc[i][1], qv.x, k1.x); fma2(acc[i][1], qv.y, k1.y);
                fma2(acc[i][2], qv.x, k2.x); fma2(acc[i][2], qv.y, k2.y);
            }
        }

        if (ec == 7) {   // pass complete: horizontal add, write P slice, reset
            #pragma unroll
            for (int i = 0; i < 4; i++) {
                #pragma unroll
                for (int j = 0; j < 3; j++) {
                    float2 f = unpack2(acc[i][j]);
                    sm[P_OFF + (h1 * TL + lq + i * 8) * SP
                             + sp * 48 + hq * 12 + sq * 3 + j] = f.x + f.y;
                    acc[i][j] = 0ull;
                }
            }
        }
    }
    __syncthreads();     // P complete; Q/K buffers now dead

    // ---- V staging (16B cp.async), 2 buffers alias the Q/K region
    auto stageV = [&](int c, int b) {
        #pragma unroll
        for (int rr = 0; rr < 2; rr++) {          // 8h*12s*16dg = 1536 float4
            const int fidx = tid + rr * 1024;
            if (rr == 0 || tid < 512) {
                const int hh = fidx / 192;
                const int rem = fidx - hh * 192;
                const int s = rem >> 4, dg = rem & 15;
                cp16(smb + (uint32_t)(b * VBSZ + (hh * VCHS + s) * VST + dg * 4) * 4u,
                     vg + (((size_t)bn * SDIM + c * VCHS + s) * HDIM + hh) * DDIM + dg * 4);
            }
        }
        cp_commit();
    };
    stageV(0, 0);
    stageV(1, 1);   // fly during phase 2 + softmax

    // ================= Phase 2: +mask +attn_scores, LayerNorm over H, write scores
    {
        const size_t as_bn = (size_t)bn * HDIM * LDIM * SDIM;
        #pragma unroll 1
        for (int it = 0; it < (TL * SDIM) / 1024; it++) {
            const int idx = tid + it * 1024;
            const int l = idx / SDIM;
            const int s = idx - l * SDIM;
            const float mk = maskg[(l0 + l) * SDIM + s];
            const size_t base = as_bn + (size_t)(l0 + l) * SDIM + s;

            float x[8];
            float mean = 0.f;
            #pragma unroll
            for (int hh = 0; hh < 8; hh++) {
                float val = sm[P_OFF + (hh * TL + l) * SP + s] + mk
                          + asg[base + (size_t)hh * LDIM * SDIM];
                x[hh] = val;
                mean += val;
            }
            mean *= 0.125f;
            float var = 0.f;
            #pragma unroll
            for (int hh = 0; hh < 8; hh++) { float d = x[hh] - mean; var += d * d; }
            var *= 0.125f;
            const float rstd = rsqrtf(var + 1e-5f);
            #pragma unroll
            for (int hh = 0; hh < 8; hh++) {
                float sc = (x[hh] - mean) * rstd * sm[GB_OFF + hh] + sm[GB_OFF + 8 + hh];
                scores_out[base + (size_t)hh * LDIM * SDIM] = sc;
                sm[P_OFF + (hh * TL + l) * SP + s] = sc;
            }
        }
    }
    __syncthreads();

    // ================= Softmax over s (temp=1/8): warp handles 8 rows via shfl
    {
        #pragma unroll 1
        for (int r8 = 0; r8 < 8; r8++) {
            float* row = sm + P_OFF + (warp * 8 + r8) * SP;
            float v0 = row[lane], v1 = row[lane + 32], v2 = row[lane + 64];
            float m = fmaxf(v0, fmaxf(v1, v2));
            #pragma unroll
            for (int off = 16; off > 0; off >>= 1)
                m = fmaxf(m, __shfl_xor_sync(0xffffffffu, m, off));
            float e0 = __expf((v0 - m) * 0.125f);
            float e1 = __expf((v1 - m) * 0.125f);
            float e2 = __expf((v2 - m) * 0.125f);
            float sum = e0 + e1 + e2;
            #pragma unroll
            for (int off = 16; off > 0; off >>= 1)
                sum += __shfl_xor_sync(0xffffffffu, sum, off);
            const float inv = 1.f / sum;
            row[lane] = e0 * inv; row[lane + 32] = e1 * inv; row[lane + 64] = e2 * inv;
        }
    }

    // ================= Phase 3: O = A.V  (warp=(h,d-quarter), lane: 4l x 4d, ss-paired)
    {
        ull o[4][2];
        #pragma unroll
        for (int i = 0; i < 4; i++) { o[i][0] = 0ull; o[i][1] = 0ull; }

        const float* ab0 = sm + P_OFF + (h1 * TL + lq) * SP;
        const float* vb0 = sm + h1 * (VCHS * VST) + hq * 16 + sq * 4;

        #pragma unroll 1
        for (int c = 0; c < 8; c++) {
            if (c < 7) cp_wait<1>(); else cp_wait<0>();
            __syncthreads();          // chunk c visible (also orders softmax at c=0)

            const float* ab = ab0 + c * VCHS;
            const float* vb = vb0 + (c & 1) * VBSZ;
            #pragma unroll
            for (int ss = 0; ss < VCHS; ss += 2) {
                ull ap[4];
                #pragma unroll
                for (int i = 0; i < 4; i++)
                    ap[i] = *reinterpret_cast<const ull*>(ab + i * 8 * SP + ss);
                const ulonglong2 v0 = *reinterpret_cast<const ulonglong2*>(vb + ss * VST);
                const ulonglong2 v1 = *reinterpret_cast<const ulonglong2*>(vb + (ss + 1) * VST);
                #pragma unroll
                for (int i = 0; i < 4; i++) {
                    float2 af = unpack2(ap[i]);
                    ull a0 = pack2(af.x), a1 = pack2(af.y);
                    fma2(o[i][0], a0, v0.x); fma2(o[i][1], a0, v0.y);
                    fma2(o[i][0], a1, v1.x); fma2(o[i][1], a1, v1.y);
                }
            }
            if (c < 6) {
                __syncthreads();          // all reads of buf (c&1) done
                stageV(c + 2, c & 1);
            }
        }

        // write O -> vout [bn][l][h][d], l = lq + 8i
        #pragma unroll
        for (int i = 0; i < 4; i++) {
            float2 r0 = unpack2(o[i][0]);
            float2 r1 = unpack2(o[i][1]);
            float4 f = make_float4(r0.x, r0.y, r1.x, r1.y);
            *reinterpret_cast<float4*>(
                vout + (((size_t)bn * LDIM + l0 + lq + i * 8) * HDIM + h1) * DDIM
                     + hq * 16 + sq * 4) = f;
        }
    }
}

extern "C" void kernel_launch(void* const* d_in, const int* in_sizes, int n_in,
                              void* d_out, int out_size) {
    const float* q     = (const float*)d_in[0];
    const float* k     = (const float*)d_in[1];
    const float* v     = (const float*)d_in[2];
    const float* mask  = (const float*)d_in[3];
    const float* ascr  = (const float*)d_in[4];
    const float* gamma = (const float*)d_in[5];
    const float* beta  = (const float*)d_in[6];

    float* scores = (float*)d_out;
    float* vo     = scores + SCORES_ELEMS;

    cudaFuncSetAttribute(stadd_kernel,
                         cudaFuncAttributeMaxDynamicSharedMemorySize, SMEM_BYTES);
    stadd_kernel<<<BNTOT * 3, 1024, SMEM_BYTES>>>(q, k, v, mask, ascr, gamma, beta,
                                                  scores, vo);
}

// round 13
// speedup vs baseline: 1.1694x; 1.1694x over previous
#include <cuda_runtime.h>
#include <cstdint>

// Shapes (fixed by this problem instance)
#define BNTOT 828      // B*N
#define LDIM 96
#define SDIM 96
#define HDIM 8
#define EDIM 64
#define DDIM 64

#define TL   24        // l-rows per CTA (4 tiles per bn)
#define ECH  8         // e per chunk (8 rounds), phase 1 (full S per round)
#define VCHS 6         // s per V chunk (16 chunks), phase 3

// smem strides (floats)
#define QST 26         // Q [h][e'][l]  (24 l + 2 pad)
#define KST 98         // K [h][e'][s]  (96 s + 2 pad)
#define VST 68         // V [h][s][d]   (64 d + 4 pad)
#define SP  98         // P [h][l][s]   (96 s + 2 pad, even -> aligned ss-pairs)

// smem float offsets
#define QBSZ   (HDIM*ECH*QST)        // 1664
#define K_OFF  QBSZ
#define KBSZ   (HDIM*ECH*KST)        // 6272
#define STAGE_SZ (QBSZ + KBSZ)       // 7936 (V double-buffer aliases this: 2*3264=6528)
#define VBSZ   (HDIM*VCHS*VST)       // 3264
#define P_OFF  STAGE_SZ              // 7936
#define P_SZ   (HDIM*TL*SP)          // 18816
#define GB_OFF (P_OFF + P_SZ)        // 26752
#define SMEM_FLOATS (GB_OFF + 16)    // 26768
#define SMEM_BYTES  (SMEM_FLOATS*4)  // 107072 B  -> 2 CTAs/SM

#define SCORES_ELEMS ((size_t)BNTOT * HDIM * LDIM * SDIM)

typedef unsigned long long ull;

__device__ __forceinline__ ull pack2(float x) {
    ull r;
    asm("mov.b64 %0, {%1, %1};" : "=l"(r) : "f"(x));
    return r;
}
__device__ __forceinline__ void fma2(ull &d, ull a, ull b) {
    asm("fma.rn.f32x2 %0, %1, %2, %0;" : "+l"(d) : "l"(a), "l"(b));
}
__device__ __forceinline__ float2 unpack2(ull a) {
    float2 f;
    asm("mov.b64 {%0, %1}, %2;" : "=f"(f.x), "=f"(f.y) : "l"(a));
    return f;
}
__device__ __forceinline__ void cp16(uint32_t dst, const float* src) {
    asm volatile("cp.async.ca.shared.global [%0], [%1], 16;" :: "r"(dst), "l"(src));
}
__device__ __forceinline__ void cp_commit() {
    asm volatile("cp.async.commit_group;" ::: "memory");
}
template <int N> __device__ __forceinline__ void cp_wait() {
    asm volatile("cp.async.wait_group %0;" :: "n"(N) : "memory");
}

__global__ __launch_bounds__(512, 2)
void stadd_kernel(const float* __restrict__ qg,
                  const float* __restrict__ kg,
                  const float* __restrict__ vg,
                  const float* __restrict__ maskg,
                  const float* __restrict__ asg,
                  const float* __restrict__ gammag,
                  const float* __restrict__ betag,
                  float* __restrict__ scores_out,
                  float* __restrict__ vout)
{
    extern __shared__ float sm[];
    const uint32_t smb = (uint32_t)__cvta_generic_to_shared(sm);
    const int bn   = blockIdx.x >> 2;
    const int lt   = blockIdx.x & 3;
    const int l0   = lt * TL;
    const int tid  = threadIdx.x;
    const int warp = tid >> 5;
    const int lane = tid & 31;
    const int h1   = warp >> 1;   // head (2 warps per head)
    const int half = warp & 1;    // s-half (ph1: 48) / d-half (ph3: 32)
    const int lq   = lane >> 3;   // 0..3 -> 6 l rows each (l = lq*6 + ...)
    const int sq   = lane & 7;    // 0..7 -> 6 s (ph1) / 4 d (ph3)

    if (tid < HDIM) { sm[GB_OFF + tid] = gammag[tid]; sm[GB_OFF + 8 + tid] = betag[tid]; }

    // ================= Phase 1: P = Q.K  (outer product, full S, e-chunks of 8)
    // warp = (h, s-half of 48); lane tile 6l x 6s; acc pairs along l.
    ull acc[3][6];
    #pragma unroll
    for (int i = 0; i < 3; i++)
        #pragma unroll
        for (int j = 0; j < 6; j++) acc[i][j] = 0ull;

    const float* qb = sm + h1 * (ECH * QST) + lq * 6;
    const float* kb = sm + K_OFF + h1 * (ECH * KST) + half * 48 + sq * 6;

    #pragma unroll 1
    for (int ec = 0; ec < 8; ec++) {
        // ---- stage K chunk (transpose): 8h*96s*2 float4 = 1536 -> 3 per thread
        __syncthreads();                          // previous round's reads done
        #pragma unroll
        for (int r = 0; r < 3; r++) {
            const int fidx = tid + r * 512;
            const int hh = fidx / 192;
            const int rem = fidx - hh * 192;
            const int s = rem >> 1, e4 = rem & 1;
            const float4 f = *reinterpret_cast<const float4*>(
                kg + (((size_t)bn * SDIM + s) * HDIM + hh) * EDIM + ec * ECH + e4 * 4);
            float* d = sm + K_OFF + hh * (ECH * KST) + (e4 * 4) * KST + s;
            d[0] = f.x; d[KST] = f.y; d[2*KST] = f.z; d[3*KST] = f.w;
        }
        // ---- stage Q chunk (transpose): 8h*24l*2 float4 = 384 -> tid<384
        if (tid < 384) {
            const int hh = tid / 48;
            const int rem = tid - hh * 48;
            const int l = rem >> 1, e4 = rem & 1;
            const float4 f = *reinterpret_cast<const float4*>(
                qg + (((size_t)bn * LDIM + l0 + l) * HDIM + hh) * EDIM + ec * ECH + e4 * 4);
            float* d = sm + hh * (ECH * QST) + (e4 * 4) * QST + l;
            d[0] = f.x; d[QST] = f.y; d[2*QST] = f.z; d[3*QST] = f.w;
        }
        __syncthreads();

        #pragma unroll
        for (int e = 0; e < ECH; e++) {
            const ull q0 = *reinterpret_cast<const ull*>(qb + e * QST);
            const ull q1 = *reinterpret_cast<const ull*>(qb + e * QST + 2);
            const ull q2 = *reinterpret_cast<const ull*>(qb + e * QST + 4);
            const float2 ka = *reinterpret_cast<const float2*>(kb + e * KST);
            const float2 kc = *reinterpret_cast<const float2*>(kb + e * KST + 2);
            const float2 ke = *reinterpret_cast<const float2*>(kb + e * KST + 4);
            ull k0 = pack2(ka.x), k1 = pack2(ka.y), k2 = pack2(kc.x);
            ull k3 = pack2(kc.y), k4 = pack2(ke.x), k5 = pack2(ke.y);
            fma2(acc[0][0], q0, k0); fma2(acc[1][0], q1, k0); fma2(acc[2][0], q2, k0);
            fma2(acc[0][1], q0, k1); fma2(acc[1][1], q1, k1); fma2(acc[2][1], q2, k1);
            fma2(acc[0][2], q0, k2); fma2(acc[1][2], q1, k2); fma2(acc[2][2], q2, k2);
            fma2(acc[0][3], q0, k3); fma2(acc[1][3], q1, k3); fma2(acc[2][3], q2, k3);
            fma2(acc[0][4], q0, k4); fma2(acc[1][4], q1, k4); fma2(acc[2][4], q2, k4);
            fma2(acc[0][5], q0, k5); fma2(acc[1][5], q1, k5); fma2(acc[2][5], q2, k5);
        }
    }

    // store accumulators -> P (pairs along l)
    #pragma unroll
    for (int i = 0; i < 3; i++) {
        #pragma unroll
        for (int j = 0; j < 6; j++) {
            float2 f = unpack2(acc[i][j]);
            const int l = lq * 6 + i * 2;
            const int s = half * 48 + sq * 6 + j;
            float* p = sm + P_OFF + (h1 * TL + l) * SP + s;
            p[0]  = f.x;
            p[SP] = f.y;
        }
    }
    __syncthreads();     // P complete; Q/K staging region now dead

    // ---- V staging (16B cp.async) into the dead Q/K region, double-buffered
    auto stageV = [&](int c, int b) {
        if (tid < 256) {
            #pragma unroll
            for (int rr = 0; rr < 3; rr++) {
                const int fidx = tid + rr * 256;
                const int hh = fidx / 96;
                const int rem = fidx - hh * 96;
                const int s = rem >> 4, dg = rem & 15;
                cp16(smb + (uint32_t)(b * VBSZ + (hh * VCHS + s) * VST + dg * 4) * 4u,
                     vg + (((size_t)bn * SDIM + c * VCHS + s) * HDIM + hh) * DDIM + dg * 4);
            }
        }
        cp_commit();
    };
    stageV(0, 0);
    stageV(1, 1);   // fly during phase 2 + softmax

    // ================= Phase 2: +mask +attn_scores, LayerNorm over H, write scores
    {
        const size_t as_bn = (size_t)bn * HDIM * LDIM * SDIM;
        #pragma unroll 1
        for (int it = 0; it < 5; it++) {
            const int idx = tid + it * 512;
            if (idx < TL * SDIM) {
                const int l = idx / SDIM;
                const int s = idx - l * SDIM;
                const float mk = maskg[(l0 + l) * SDIM + s];
                const size_t base = as_bn + (size_t)(l0 + l) * SDIM + s;

                float x[8];
                float mean = 0.f;
                #pragma unroll
                for (int hh = 0; hh < 8; hh++) {
                    float val = sm[P_OFF + (hh * TL + l) * SP + s] + mk
                              + asg[base + (size_t)hh * LDIM * SDIM];
                    x[hh] = val;
                    mean += val;
                }
                mean *= 0.125f;
                float var = 0.f;
                #pragma unroll
                for (int hh = 0; hh < 8; hh++) { float d = x[hh] - mean; var += d * d; }
                var *= 0.125f;
                const float rstd = rsqrtf(var + 1e-5f);
                #pragma unroll
                for (int hh = 0; hh < 8; hh++) {
                    float sc = (x[hh] - mean) * rstd * sm[GB_OFF + hh] + sm[GB_OFF + 8 + hh];
                    scores_out[base + (size_t)hh * LDIM * SDIM] = sc;
                    sm[P_OFF + (hh * TL + l) * SP + s] = sc;
                }
            }
        }
    }
    __syncthreads();

    // ================= Softmax over s (temp=1/8): 192 rows, 12 per warp
    {
        #pragma unroll 1
        for (int rr = 0; rr < 12; rr++) {
            float* row = sm + P_OFF + (warp * 12 + rr) * SP;
            float v0 = row[lane], v1 = row[lane + 32], v2 = row[lane + 64];
            float m = fmaxf(v0, fmaxf(v1, v2));
            #pragma unroll
            for (int off = 16; off > 0; off >>= 1)
                m = fmaxf(m, __shfl_xor_sync(0xffffffffu, m, off));
            float e0 = __expf((v0 - m) * 0.125f);
            float e1 = __expf((v1 - m) * 0.125f);
            float e2 = __expf((v2 - m) * 0.125f);
            float sum = e0 + e1 + e2;
            #pragma unroll
            for (int off = 16; off > 0; off >>= 1)
                sum += __shfl_xor_sync(0xffffffffu, sum, off);
            const float inv = 1.f / sum;
            row[lane] = e0 * inv; row[lane + 32] = e1 * inv; row[lane + 64] = e2 * inv;
        }
    }

    // ================= Phase 3: O = A.V  (warp=(h,d-half), lane 6l x 4d, ss-paired)
    {
        ull o[6][2];
        #pragma unroll
        for (int i = 0; i < 6; i++) { o[i][0] = 0ull; o[i][1] = 0ull; }

        const float* ab0 = sm + P_OFF + (h1 * TL + lq * 6) * SP;
        const float* vb0 = sm + h1 * (VCHS * VST) + half * 32 + sq * 4;

        #pragma unroll 1
        for (int c = 0; c < 16; c++) {
            if (c < 15) cp_wait<1>(); else cp_wait<0>();
            __syncthreads();          // chunk c visible (also orders softmax at c=0)

            const float* ab = ab0 + c * VCHS;
            const float* vb = vb0 + (c & 1) * VBSZ;
            #pragma unroll
            for (int ss = 0; ss < VCHS; ss += 2) {
                ull ap[6];
                #pragma unroll
                for (int i = 0; i < 6; i++)
                    ap[i] = *reinterpret_cast<const ull*>(ab + i * SP + ss);
                const ulonglong2 v0 = *reinterpret_cast<const ulonglong2*>(vb + ss * VST);
                const ulonglong2 v1 = *reinterpret_cast<const ulonglong2*>(vb + (ss + 1) * VST);
                #pragma unroll
                for (int i = 0; i < 6; i++) {
                    float2 af = unpack2(ap[i]);
                    ull a0 = pack2(af.x), a1 = pack2(af.y);
                    fma2(o[i][0], a0, v0.x); fma2(o[i][1], a0, v0.y);
                    fma2(o[i][0], a1, v1.x); fma2(o[i][1], a1, v1.y);
                }
            }
            if (c < 14) {
                __syncthreads();          // all reads of buf (c&1) done
                stageV(c + 2, c & 1);
            }
        }

        // write O -> vout [bn][l][h][d], l = lq*6 + i
        #pragma unroll
        for (int i = 0; i < 6; i++) {
            float2 r0 = unpack2(o[i][0]);
            float2 r1 = unpack2(o[i][1]);
            float4 f = make_float4(r0.x, r0.y, r1.x, r1.y);
            *reinterpret_cast<float4*>(
                vout + (((size_t)bn * LDIM + l0 + lq * 6 + i) * HDIM + h1) * DDIM
                     + half * 32 + sq * 4) = f;
        }
    }
}

extern "C" void kernel_launch(void* const* d_in, const int* in_sizes, int n_in,
                              void* d_out, int out_size) {
    const float* q     = (const float*)d_in[0];
    const float* k     = (const float*)d_in[1];
    const float* v     = (const float*)d_in[2];
    const float* mask  = (const float*)d_in[3];
    const float* ascr  = (const float*)d_in[4];
    const float* gamma = (const float*)d_in[5];
    const float* beta  = (const float*)d_in[6];

    float* scores = (float*)d_out;
    float* vo     = scores + SCORES_ELEMS;

    cudaFuncSetAttribute(stadd_kernel,
                         cudaFuncAttributeMaxDynamicSharedMemorySize, SMEM_BYTES);
    stadd_kernel<<<BNTOT * 4, 512, SMEM_BYTES>>>(q, k, v, mask, ascr, gamma, beta,
                                                 scores, vo);
}